// round 5
// baseline (speedup 1.0000x reference)
#include <cuda_runtime.h>

#define N_SAMP 384
#define M 12
#define NP 6
#define UC (M * NP)      // 72 complex entries per sample

// g_u1[i][k][b] = U1_i[k][b] ; g_u2[j][k][a] = conj(U2_j[k][a])
__device__ float2 g_u1[N_SAMP * UC];
__device__ float2 g_u2[N_SAMP * UC];

__device__ __forceinline__ float2 cmul(float2 a, float2 b) {
    return make_float2(a.x * b.x - a.y * b.y, a.x * b.y + a.y * b.x);
}

// ---------------------------------------------------------------------------
// Stage 1 (single launch, grid=768): U(x) = A @ diag(exp(ix)) @ B, first NP cols.
// Blocks [0,384) -> x1 -> g_u1 ; blocks [384,768) -> x2 -> conj -> g_u2.
// ---------------------------------------------------------------------------
__global__ void build_u_kernel(const float* __restrict__ x1,
                               const float* __restrict__ x2,
                               const float* __restrict__ A_re,
                               const float* __restrict__ A_im,
                               const float* __restrict__ B_re,
                               const float* __restrict__ B_im)
{
    __shared__ float2 ph[M];
    __shared__ float2 sA[M * M];
    __shared__ float2 sB[M][NP];

    const int s      = blockIdx.x;
    const int tid    = threadIdx.x;
    const int second = (s >= N_SAMP);
    const int ss     = second ? s - N_SAMP : s;
    const float* x   = second ? x2 : x1;

    if (tid < M * M) sA[tid] = make_float2(A_re[tid], A_im[tid]);
    if (tid < M * NP) {
        int b = tid / NP, c = tid - b * NP;
        sB[b][c] = make_float2(B_re[b * M + c], B_im[b * M + c]);
    }
    if (tid < M) {
        float sn, cs;
        sincosf(x[ss * M + tid], &sn, &cs);
        ph[tid] = make_float2(cs, sn);
    }
    __syncthreads();

    if (tid < M * NP) {
        const int a = tid / NP;
        const int c = tid - a * NP;
        float2 acc = make_float2(0.f, 0.f);
#pragma unroll
        for (int b = 0; b < M; ++b) {
            float2 t  = cmul(ph[b], sB[b][c]);
            float2 Av = sA[a * M + b];
            acc.x += Av.x * t.x - Av.y * t.y;
            acc.y += Av.x * t.y + Av.y * t.x;
        }
        if (second) {
            acc.y = -acc.y;
            g_u2[ss * UC + tid] = acc;
        } else {
            g_u1[ss * UC + tid] = acc;
        }
    }
}

// ---------------------------------------------------------------------------
// Stage 2: per pair (i,j): W[a][b] = sum_k conjU2[j][k][a] * U1[i][k][b],
// then Glynn permanent (single Gray chain), K = |perm|^2.
// 8(i) x 16(j) pair tile per 128-thread block (fine occupancy granularity).
// ---------------------------------------------------------------------------
#define SPITCH 73   // per-sample smem pitch (float2): conflict-free row stride

#define TI 8
#define TJ 16

__device__ __forceinline__ float2 prod6(const float2* r) {
    float2 p01 = cmul(r[0], r[1]);
    float2 p23 = cmul(r[2], r[3]);
    float2 p45 = cmul(r[4], r[5]);
    return cmul(cmul(p01, p23), p45);
}

__global__ __launch_bounds__(128) void pair_kernel(float* __restrict__ out)
{
    __shared__ float2 s1[TI * SPITCH];
    __shared__ float2 s2[TJ * SPITCH];

    const int i0  = blockIdx.y * TI;
    const int j0  = blockIdx.x * TJ;
    const int tid = threadIdx.x;

    for (int e = tid; e < TI * UC; e += 128) {
        int l = e / UC;
        int r = e - l * UC;
        s1[l * SPITCH + r] = g_u1[(i0 + l) * UC + r];
    }
    for (int e = tid; e < TJ * UC; e += 128) {
        int l = e / UC;
        int r = e - l * UC;
        s2[l * SPITCH + r] = g_u2[(j0 + l) * UC + r];
    }
    __syncthreads();

    const int lj = tid & 15;        // j fastest -> coalesced output
    const int li = tid >> 4;        // 0..7
    const float2* __restrict__ p1 = &s1[li * SPITCH];
    const float2* __restrict__ p2 = &s2[lj * SPITCH];

    float2 W[NP][NP];
#pragma unroll
    for (int a = 0; a < NP; ++a)
#pragma unroll
        for (int b = 0; b < NP; ++b)
            W[a][b] = make_float2(0.f, 0.f);

    // GEMM with minimal live temps: b6[6] + one 'a' operand at a time.
#pragma unroll
    for (int k = 0; k < M; ++k) {
        float2 b6[NP];
#pragma unroll
        for (int b = 0; b < NP; ++b) b6[b] = p1[k * NP + b];
#pragma unroll
        for (int a = 0; a < NP; ++a) {
            const float2 av = p2[k * NP + a];
#pragma unroll
            for (int b = 0; b < NP; ++b) {
                W[a][b].x += av.x * b6[b].x - av.y * b6[b].y;
                W[a][b].y += av.x * b6[b].y + av.y * b6[b].x;
            }
        }
    }

    // --- Glynn permanent, n=6, single Gray chain (32 sign vectors) ---
    float2 r[NP];
#pragma unroll
    for (int j = 0; j < NP; ++j) {
        float2 t = W[0][j];
#pragma unroll
        for (int a = 1; a < NP; ++a) {
            t.x += W[a][j].x;
            t.y += W[a][j].y;
        }
        r[j] = t;
    }

    float2 acc = prod6(r);

#pragma unroll
    for (int t = 1; t < 32; ++t) {
        const int bit = (t & 1) ? 0 : ((t & 2) ? 1 : ((t & 4) ? 2 : ((t & 8) ? 3 : 4)));
        const int a   = bit + 1;                              // flipped row (1..5)
        const float s2v = (((t ^ (t >> 1)) >> bit) & 1) ? -2.f : 2.f;
        const float sg  = (t & 1) ? -1.f : 1.f;               // parity (-1)^t

#pragma unroll
        for (int j = 0; j < NP; ++j) {
            r[j].x += s2v * W[a][j].x;
            r[j].y += s2v * W[a][j].y;
        }
        float2 p = prod6(r);
        acc.x += sg * p.x;
        acc.y += sg * p.y;
    }

    // perm = acc / 32 ; K = |perm|^2 = |acc|^2 / 1024
    const float K = (acc.x * acc.x + acc.y * acc.y) * (1.0f / 1024.0f);
    out[(i0 + li) * N_SAMP + (j0 + lj)] = K;
}

// ---------------------------------------------------------------------------
extern "C" void kernel_launch(void* const* d_in, const int* in_sizes, int n_in,
                              void* d_out, int out_size)
{
    const float* x1   = (const float*)d_in[0];
    const float* x2   = (const float*)d_in[1];
    const float* A_re = (const float*)d_in[2];
    const float* A_im = (const float*)d_in[3];
    const float* B_re = (const float*)d_in[4];
    const float* B_im = (const float*)d_in[5];

    build_u_kernel<<<2 * N_SAMP, 160>>>(x1, x2, A_re, A_im, B_re, B_im);

    dim3 grid(N_SAMP / TJ, N_SAMP / TI);   // 24 x 48
    pair_kernel<<<grid, 128>>>((float*)d_out);
}

// round 6
// speedup vs baseline: 1.3946x; 1.3946x over previous
#include <cuda_runtime.h>

#define N_SAMP 384
#define M 12
#define NP 6
#define UC (M * NP)      // 72 complex entries per sample

typedef unsigned long long u64;

// Duplicated packed operand formats (built once in stage 1):
// g_u1d entry e=(k*6+b): [2e]   = (re, im)        = bp
//                        [2e+1] = (-im, re)       = bn
// g_u2d entry e=(k*6+a): [2e]   = (cre, cre)      = aR   (c = conj(U2))
//                        [2e+1] = (cim, cim)      = aI
// Then cmul(c, u1) = aR .* bp + aI .* bn  (two packed FFMA2).
__device__ float2 g_u1d[N_SAMP * UC * 2];
__device__ float2 g_u2d[N_SAMP * UC * 2];

__device__ __forceinline__ float2 cmul(float2 a, float2 b) {
    return make_float2(a.x * b.x - a.y * b.y, a.x * b.y + a.y * b.x);
}

// ---- packed f32x2 helpers ----
__device__ __forceinline__ u64 pk2(float lo, float hi) {
    u64 d; asm("mov.b64 %0, {%1,%2};" : "=l"(d) : "f"(lo), "f"(hi)); return d;
}
__device__ __forceinline__ float2 upk(u64 d) {
    float2 r; asm("mov.b64 {%0,%1}, %2;" : "=f"(r.x), "=f"(r.y) : "l"(d)); return r;
}
__device__ __forceinline__ u64 ffma2(u64 a, u64 b, u64 c) {
    u64 d; asm("fma.rn.f32x2 %0, %1, %2, %3;" : "=l"(d) : "l"(a), "l"(b), "l"(c)); return d;
}
__device__ __forceinline__ u64 fadd2(u64 a, u64 b) {
    u64 d; asm("add.rn.f32x2 %0, %1, %2;" : "=l"(d) : "l"(a), "l"(b)); return d;
}

// ---------------------------------------------------------------------------
// Stage 1 (single launch, grid=768): U(x) = A @ diag(exp(ix)) @ B, first NP cols,
// written out in the duplicated packed formats above.
// ---------------------------------------------------------------------------
__global__ void build_u_kernel(const float* __restrict__ x1,
                               const float* __restrict__ x2,
                               const float* __restrict__ A_re,
                               const float* __restrict__ A_im,
                               const float* __restrict__ B_re,
                               const float* __restrict__ B_im)
{
    __shared__ float2 ph[M];
    __shared__ float2 sA[M * M];
    __shared__ float2 sB[M][NP];

    const int s      = blockIdx.x;
    const int tid    = threadIdx.x;
    const int second = (s >= N_SAMP);
    const int ss     = second ? s - N_SAMP : s;
    const float* x   = second ? x2 : x1;

    if (tid < M * M) sA[tid] = make_float2(A_re[tid], A_im[tid]);
    if (tid < M * NP) {
        int b = tid / NP, c = tid - b * NP;
        sB[b][c] = make_float2(B_re[b * M + c], B_im[b * M + c]);
    }
    if (tid < M) {
        float sn, cs;
        sincosf(x[ss * M + tid], &sn, &cs);
        ph[tid] = make_float2(cs, sn);
    }
    __syncthreads();

    if (tid < M * NP) {
        const int a = tid / NP;
        const int c = tid - a * NP;
        float2 acc = make_float2(0.f, 0.f);
#pragma unroll
        for (int b = 0; b < M; ++b) {
            float2 t  = cmul(ph[b], sB[b][c]);
            float2 Av = sA[a * M + b];
            acc.x += Av.x * t.x - Av.y * t.y;
            acc.y += Av.x * t.y + Av.y * t.x;
        }
        const int base = (ss * UC + tid) * 2;
        if (second) {
            // conj: (acc.x, -acc.y) -> aR=(re,re), aI=(im,im)
            g_u2d[base + 0] = make_float2(acc.x, acc.x);
            g_u2d[base + 1] = make_float2(-acc.y, -acc.y);
        } else {
            // bp=(re,im), bn=(-im,re)
            g_u1d[base + 0] = make_float2(acc.x, acc.y);
            g_u1d[base + 1] = make_float2(-acc.y, acc.x);
        }
    }
}

// ---------------------------------------------------------------------------
// Stage 2: per pair (i,j): W[a][b] = sum_k conjU2[j][k][a] * U1[i][k][b] via
// pure FFMA2, then Glynn permanent (single Gray chain, packed rowsums).
// 16x16 pair tile per 256-thread block.
// ---------------------------------------------------------------------------
#define SP 145   // smem pitch in u64 for rows of 144 (odd -> conflict-free)

__device__ __forceinline__ float2 prod6(const u64* r) {
    float2 a0 = upk(r[0]), a1 = upk(r[1]), a2 = upk(r[2]);
    float2 a3 = upk(r[3]), a4 = upk(r[4]), a5 = upk(r[5]);
    float2 p01 = cmul(a0, a1);
    float2 p23 = cmul(a2, a3);
    float2 p45 = cmul(a4, a5);
    return cmul(cmul(p01, p23), p45);
}

__global__ __launch_bounds__(256) void pair_kernel(float* __restrict__ out)
{
    __shared__ u64 s1[16 * SP];
    __shared__ u64 s2[16 * SP];

    const int i0  = blockIdx.y * 16;
    const int j0  = blockIdx.x * 16;
    const int tid = threadIdx.x;

    const u64* __restrict__ gu1 = (const u64*)g_u1d;
    const u64* __restrict__ gu2 = (const u64*)g_u2d;
    for (int e = tid; e < 16 * (UC * 2); e += 256) {
        int l = e / (UC * 2);
        int r = e - l * (UC * 2);
        s1[l * SP + r] = gu1[(i0 + l) * (UC * 2) + r];
        s2[l * SP + r] = gu2[(j0 + l) * (UC * 2) + r];
    }
    __syncthreads();

    const int lj = tid & 15;        // j fastest -> coalesced output
    const int li = tid >> 4;
    const u64* __restrict__ p1 = &s1[li * SP];   // bp/bn pairs
    const u64* __restrict__ p2 = &s2[lj * SP];   // aR/aI pairs

    u64 W[NP][NP];
#pragma unroll
    for (int a = 0; a < NP; ++a)
#pragma unroll
        for (int b = 0; b < NP; ++b)
            W[a][b] = 0ull;   // two packed fp32 zeros

#pragma unroll
    for (int k = 0; k < M; ++k) {
        u64 bb[12];               // bp0,bn0,bp1,bn1,... batch-loaded for ILP
#pragma unroll
        for (int e = 0; e < 12; ++e) bb[e] = p1[k * 12 + e];
#pragma unroll
        for (int a = 0; a < NP; ++a) {
            const u64 aR = p2[k * 12 + 2 * a + 0];
            const u64 aI = p2[k * 12 + 2 * a + 1];
#pragma unroll
            for (int b = 0; b < NP; ++b) {
                W[a][b] = ffma2(aR, bb[2 * b + 0], W[a][b]);
                W[a][b] = ffma2(aI, bb[2 * b + 1], W[a][b]);
            }
        }
    }

    // --- Glynn permanent, n=6, single Gray chain, packed rowsums ---
    const u64 PL2 = pk2(2.f, 2.f);
    const u64 MI2 = pk2(-2.f, -2.f);

    u64 r[NP];
#pragma unroll
    for (int j = 0; j < NP; ++j) {
        u64 t01 = fadd2(W[0][j], W[1][j]);
        u64 t23 = fadd2(W[2][j], W[3][j]);
        u64 t45 = fadd2(W[4][j], W[5][j]);
        r[j] = fadd2(fadd2(t01, t23), t45);
    }

    float2 acc = prod6(r);

#pragma unroll
    for (int t = 1; t < 32; ++t) {
        const int bit = (t & 1) ? 0 : ((t & 2) ? 1 : ((t & 4) ? 2 : ((t & 8) ? 3 : 4)));
        const int a   = bit + 1;                              // flipped row (1..5)
        const bool neg = (((t ^ (t >> 1)) >> bit) & 1) != 0;
        const u64 c2  = neg ? MI2 : PL2;
        const float sg = (t & 1) ? -1.f : 1.f;                // parity (-1)^t

#pragma unroll
        for (int j = 0; j < NP; ++j)
            r[j] = ffma2(c2, W[a][j], r[j]);

        float2 p = prod6(r);
        acc.x += sg * p.x;
        acc.y += sg * p.y;
    }

    // perm = acc / 32 ; K = |perm|^2 = |acc|^2 / 1024
    const float K = (acc.x * acc.x + acc.y * acc.y) * (1.0f / 1024.0f);
    out[(i0 + li) * N_SAMP + (j0 + lj)] = K;
}

// ---------------------------------------------------------------------------
extern "C" void kernel_launch(void* const* d_in, const int* in_sizes, int n_in,
                              void* d_out, int out_size)
{
    const float* x1   = (const float*)d_in[0];
    const float* x2   = (const float*)d_in[1];
    const float* A_re = (const float*)d_in[2];
    const float* A_im = (const float*)d_in[3];
    const float* B_re = (const float*)d_in[4];
    const float* B_im = (const float*)d_in[5];

    build_u_kernel<<<2 * N_SAMP, 160>>>(x1, x2, A_re, A_im, B_re, B_im);

    dim3 grid(N_SAMP / 16, N_SAMP / 16);   // 24 x 24
    pair_kernel<<<grid, 256>>>((float*)d_out);
}